// round 9
// baseline (speedup 1.0000x reference)
#include <cuda_runtime.h>
#include <cuda_bf16.h>

#define CN0 262144
#define CN1 131072
#define CN2 65536
#define CE0 2097152
#define CE1 1048576
#define CIN 128
#define CH  32
#define CEPS 1e-12f

typedef unsigned int uint;

// ---- scratch (device globals; referenced from DEVICE code only) ----
__device__ float g_y0[(size_t)CN0 * CH];
__device__ float g_r0[(size_t)CN1 * CH];
__device__ float g_h [(size_t)CN1 * CH];
__device__ float g_z1[(size_t)CN1 * CH];
__device__ float g_r1[(size_t)CN2 * CH];

__device__ __nv_bfloat16 g_whi[64 * CIN];
__device__ __nv_bfloat16 g_wlo[64 * CIN];

__device__ int g_cnt0[CN1];
__device__ int g_cur0[CN1];
__device__ int g_offl0[CN1];
__device__ int g_part0[CN1 / 1024];
__device__ int g_eid0[CE0];

__device__ int g_cnt1[CN2];
__device__ int g_cur1[CN2];
__device__ int g_offl1[CN2];
__device__ int g_part1[CN2 / 1024];
__device__ int g_eid1[CE1];

__device__ __forceinline__ uint pkbf(float a, float b) {
    __nv_bfloat162 t = __halves2bfloat162(__float2bfloat16(a), __float2bfloat16(b));
    return *reinterpret_cast<uint*>(&t);
}
__device__ __forceinline__ void mma_bf16(float* d, const uint* a, uint b0, uint b1) {
    asm volatile(
        "mma.sync.aligned.m16n8k16.row.col.f32.bf16.bf16.f32 "
        "{%0,%1,%2,%3}, {%4,%5,%6,%7}, {%8,%9}, {%0,%1,%2,%3};"
        : "+f"(d[0]), "+f"(d[1]), "+f"(d[2]), "+f"(d[3])
        : "r"(a[0]), "r"(a[1]), "r"(a[2]), "r"(a[3]), "r"(b0), "r"(b1));
}

// ============================================================
// initprep: blocks [0,384) zero cnt0/cur0/cnt1/cur1 (int4),
//           blocks [384,416) split W into bf16 hi/lo.
// ============================================================
__global__ __launch_bounds__(256) void initprep_kernel(
    const float* __restrict__ wl0, const float* __restrict__ wr0)
{
    int blk = blockIdx.x;
    if (blk < 384) {
        int t = blk * 256 + threadIdx.x;          // 98304 int4 slots
        const int4 z = make_int4(0, 0, 0, 0);
        if (t < 32768)       ((int4*)g_cnt0)[t] = z;
        else if (t < 65536)  ((int4*)g_cur0)[t - 32768] = z;
        else if (t < 81920)  ((int4*)g_cnt1)[t - 65536] = z;
        else                 ((int4*)g_cur1)[t - 81920] = z;
    } else {
        int i = (blk - 384) * 256 + threadIdx.x;  // 8192 weights
        float v = (i < 32 * CIN) ? wl0[i] : wr0[i - 32 * CIN];
        __nv_bfloat16 h = __float2bfloat16(v);
        g_whi[i] = h;
        g_wlo[i] = __float2bfloat16(v - __bfloat162float(h));
    }
}

// ============================================================
// hist_both: blocks [0,2048) layer0 edges, [2048,3072) layer1.
// ============================================================
__global__ __launch_bounds__(256) void hist_both_kernel(
    const int* __restrict__ tgt0, const int* __restrict__ tgt1)
{
    int blk = blockIdx.x;
    const int* tgt;
    int* cnt;
    int eb;
    if (blk < 2048) { tgt = tgt0; cnt = g_cnt0; eb = blk; }
    else            { tgt = tgt1; cnt = g_cnt1; eb = blk - 2048; }
    int b = (eb * 256 + threadIdx.x) * 4;
    int4 t = __ldg((const int4*)(tgt + b));
    atomicAdd(&cnt[t.x], 1);
    atomicAdd(&cnt[t.y], 1);
    atomicAdd(&cnt[t.z], 1);
    atomicAdd(&cnt[t.w], 1);
}

// ============================================================
// scanA_both: blocks [0,128) layer0 tiles, [128,192) layer1.
// ============================================================
__global__ __launch_bounds__(256) void scanA_both_kernel()
{
    int blk = blockIdx.x;
    const int* cnt;
    int* offl;
    int* part;
    int tile;
    if (blk < 128) { cnt = g_cnt0; offl = g_offl0; part = g_part0; tile = blk; }
    else           { cnt = g_cnt1; offl = g_offl1; part = g_part1; tile = blk - 128; }

    __shared__ int wsum[8];
    int tid = threadIdx.x;
    int base = tile * 1024 + tid * 4;
    int4 c = __ldg((const int4*)(cnt + base));
    int s1 = c.x + c.y, s2 = s1 + c.z, s3 = s2 + c.w;

    int lane = tid & 31, w = tid >> 5;
    int v = s3;
    #pragma unroll
    for (int o = 1; o < 32; o <<= 1) {
        int t = __shfl_up_sync(0xffffffffu, v, o);
        if (lane >= o) v += t;
    }
    int thr_excl = v - s3;
    if (lane == 31) wsum[w] = v;
    __syncthreads();
    if (w == 0) {
        int ws = (lane < 8) ? wsum[lane] : 0;
        #pragma unroll
        for (int o = 1; o < 8; o <<= 1) {
            int t = __shfl_up_sync(0xffffffffu, ws, o);
            if (lane >= o) ws += t;
        }
        if (lane < 8) wsum[lane] = ws;
    }
    __syncthreads();
    int wexcl = (w == 0) ? 0 : wsum[w - 1];
    int e = wexcl + thr_excl;

    int4 o4;
    o4.x = e; o4.y = e + c.x; o4.z = e + s1; o4.w = e + s2;
    *(int4*)(offl + base) = o4;
    if (tid == 255) part[tile] = wsum[7];
}

// ============================================================
// scanB_both: one block. threads [0,128) scan part0 (n=128),
// threads [128,192) scan part1 (n=64). Exclusive in-place.
// ============================================================
__global__ __launch_bounds__(256) void scanB_both_kernel()
{
    __shared__ int ws[8];
    int tid = threadIdx.x;
    bool L1 = tid >= 128;
    int n = L1 ? 64 : 128;
    int idx = L1 ? tid - 128 : tid;
    int* part = L1 ? g_part1 : g_part0;

    int valid = idx < n && tid < 192;
    int v = valid ? part[idx] : 0;
    int lane = tid & 31, w = tid >> 5;   // warps 0-3: L0, 4-5: L1
    int x = v;
    #pragma unroll
    for (int o = 1; o < 32; o <<= 1) {
        int t = __shfl_up_sync(0xffffffffu, x, o);
        if (lane >= o) x += t;
    }
    if (lane == 31 && w < 6) ws[w] = x;
    __syncthreads();
    if (tid == 0) {
        int a = 0;
        #pragma unroll
        for (int i = 0; i < 4; i++) { int t = ws[i]; ws[i] = a; a += t; }
    }
    if (tid == 128) {
        int a = 0;
        #pragma unroll
        for (int i = 4; i < 6; i++) { int t = ws[i]; ws[i] = a; a += t; }
    }
    __syncthreads();
    if (valid) part[idx] = (x - v) + ws[w];
}

// ============================================================
// bucket_both: pos = offl(t) + part(tile) + cur(t)++; eid[pos] = src.
// blocks [0,2048) layer0, [2048,3072) layer1.
// ============================================================
__global__ __launch_bounds__(256) void bucket_both_kernel(
    const int* __restrict__ src0, const int* __restrict__ tgt0,
    const int* __restrict__ src1, const int* __restrict__ tgt1)
{
    int blk = blockIdx.x;
    const int* src; const int* tgt;
    const int* offl; const int* part;
    int* cur; int* eid;
    int eb;
    if (blk < 2048) {
        src = src0; tgt = tgt0; offl = g_offl0; part = g_part0;
        cur = g_cur0; eid = g_eid0; eb = blk;
    } else {
        src = src1; tgt = tgt1; offl = g_offl1; part = g_part1;
        cur = g_cur1; eid = g_eid1; eb = blk - 2048;
    }

    int b = (eb * 256 + threadIdx.x) * 4;
    int4 t = __ldg((const int4*)(tgt + b));
    int4 s = __ldg((const int4*)(src + b));
    #pragma unroll
    for (int i = 0; i < 4; i++) {
        int ti = (i == 0) ? t.x : (i == 1) ? t.y : (i == 2) ? t.z : t.w;
        int si = (i == 0) ? s.x : (i == 1) ? s.y : (i == 2) ? s.z : s.w;
        int off = __ldg(offl + ti) + __ldg(part + (ti >> 10));
        int pos = off + atomicAdd(&cur[ti], 1);
        eid[pos] = si;
    }
}

// ============================================================
// gemm0: mma.sync bf16-split GEMM (unchanged from R7)
// ============================================================
#define BSTRIDE 68

__global__ __launch_bounds__(256) void gemm0_kernel(const float* __restrict__ x)
{
    __shared__ uint sbh[64 * BSTRIDE];
    __shared__ uint sbl[64 * BSTRIDE];

    int tid = threadIdx.x;
    int wid = tid >> 5, lane = tid & 31;

    {
        const uint* whi = (const uint*)g_whi;
        const uint* wlo = (const uint*)g_wlo;
        #pragma unroll
        for (int c = tid; c < 4096; c += 256) {
            int r = c >> 6, k = c & 63;
            sbh[r * BSTRIDE + k] = __ldg(whi + c);
            sbl[r * BSTRIDE + k] = __ldg(wlo + c);
        }
    }
    __syncthreads();

    int mrow = lane >> 2;
    int c = lane & 3;
    int nl = lane >> 2;

    int row0 = blockIdx.x * 128 + wid * 16 + mrow;
    const float2* x2 = (const float2*)x;
    size_t base0 = (size_t)row0 * 64 + c;
    size_t base1 = base0 + 8 * 64;

    float d[8][4];
    #pragma unroll
    for (int n = 0; n < 8; n++)
        #pragma unroll
        for (int j = 0; j < 4; j++) d[n][j] = 0.f;

    #pragma unroll
    for (int ks = 0; ks < 8; ks++) {
        float2 p0 = __ldg(&x2[base0 + ks * 8]);
        float2 p1 = __ldg(&x2[base1 + ks * 8]);
        float2 p2 = __ldg(&x2[base0 + ks * 8 + 4]);
        float2 p3 = __ldg(&x2[base1 + ks * 8 + 4]);

        uint ah[4], al[4];
        ah[0] = pkbf(p0.x, p0.y);
        ah[1] = pkbf(p1.x, p1.y);
        ah[2] = pkbf(p2.x, p2.y);
        ah[3] = pkbf(p3.x, p3.y);
        {
            __nv_bfloat162 h0 = *(__nv_bfloat162*)&ah[0];
            __nv_bfloat162 h1 = *(__nv_bfloat162*)&ah[1];
            __nv_bfloat162 h2 = *(__nv_bfloat162*)&ah[2];
            __nv_bfloat162 h3 = *(__nv_bfloat162*)&ah[3];
            al[0] = pkbf(p0.x - __bfloat162float(h0.x), p0.y - __bfloat162float(h0.y));
            al[1] = pkbf(p1.x - __bfloat162float(h1.x), p1.y - __bfloat162float(h1.y));
            al[2] = pkbf(p2.x - __bfloat162float(h2.x), p2.y - __bfloat162float(h2.y));
            al[3] = pkbf(p3.x - __bfloat162float(h3.x), p3.y - __bfloat162float(h3.y));
        }

        #pragma unroll
        for (int n = 0; n < 8; n++) {
            int bidx = (n * 8 + nl) * BSTRIDE + ks * 8 + c;
            uint bh0 = sbh[bidx], bh1 = sbh[bidx + 4];
            uint bl0 = sbl[bidx], bl1 = sbl[bidx + 4];
            mma_bf16(d[n], ah, bh0, bh1);
            mma_bf16(d[n], al, bh0, bh1);
            mma_bf16(d[n], ah, bl0, bl1);
        }
    }

    int rA = row0;
    int rB = row0 + 8;
    #pragma unroll
    for (int n = 0; n < 8; n++) {
        int col = (n & 3) * 8 + c * 2;
        if (n < 4) {
            *(float2*)(g_y0 + (size_t)rA * CH + col) = make_float2(d[n][0], d[n][1]);
            *(float2*)(g_y0 + (size_t)rB * CH + col) = make_float2(d[n][2], d[n][3]);
        } else if (rA < CN1) {
            *(float2*)(g_r0 + (size_t)rA * CH + col) = make_float2(d[n][0], d[n][1]);
            *(float2*)(g_r0 + (size_t)rB * CH + col) = make_float2(d[n][2], d[n][3]);
        }
    }
}

// ============================================================
// aggfin: warp per row; batched gather + fused finalize.
// start = offl + part (CSR base), cnt from hist.
// ============================================================
template <int LAYER>
__global__ __launch_bounds__(256) void aggfin_kernel(
    const float* __restrict__ bias, float* __restrict__ out_param)
{
    const float* table = (LAYER == 0) ? g_y0 : g_z1;
    const float* rt    = (LAYER == 0) ? g_r0 : g_r1;
    const int*   cnta  = (LAYER == 0) ? g_cnt0 : g_cnt1;
    const int*   offl  = (LAYER == 0) ? g_offl0 : g_offl1;
    const int*   part  = (LAYER == 0) ? g_part0 : g_part1;
    const int*   eid   = (LAYER == 0) ? g_eid0 : g_eid1;
    float*       out   = (LAYER == 0) ? g_h : out_param;

    int lane = threadIdx.x & 31;
    int row = blockIdx.x * 8 + (threadIdx.x >> 5);
    int g = lane >> 3;
    int f4 = lane & 7;

    int cnt = __ldg(cnta + row);
    int start = __ldg(offl + row) + __ldg(part + (row >> 10));

    float4 acc = make_float4(0.f, 0.f, 0.f, 0.f);
    int i = g;
    for (; i + 12 < cnt; i += 16) {
        int s0 = __ldg(eid + start + i);
        int s1 = __ldg(eid + start + i + 4);
        int s2 = __ldg(eid + start + i + 8);
        int s3 = __ldg(eid + start + i + 12);
        float4 v0 = __ldg((const float4*)(table + (size_t)s0 * CH) + f4);
        float4 v1 = __ldg((const float4*)(table + (size_t)s1 * CH) + f4);
        float4 v2 = __ldg((const float4*)(table + (size_t)s2 * CH) + f4);
        float4 v3 = __ldg((const float4*)(table + (size_t)s3 * CH) + f4);
        acc.x += (v0.x + v1.x) + (v2.x + v3.x);
        acc.y += (v0.y + v1.y) + (v2.y + v3.y);
        acc.z += (v0.z + v1.z) + (v2.z + v3.z);
        acc.w += (v0.w + v1.w) + (v2.w + v3.w);
    }
    for (; i < cnt; i += 4) {
        int s = __ldg(eid + start + i);
        float4 v = __ldg((const float4*)(table + (size_t)s * CH) + f4);
        acc.x += v.x; acc.y += v.y; acc.z += v.z; acc.w += v.w;
    }
    #pragma unroll
    for (int o = 8; o <= 16; o <<= 1) {
        acc.x += __shfl_xor_sync(0xffffffffu, acc.x, o);
        acc.y += __shfl_xor_sync(0xffffffffu, acc.y, o);
        acc.z += __shfl_xor_sync(0xffffffffu, acc.z, o);
        acc.w += __shfl_xor_sync(0xffffffffu, acc.w, o);
    }

    float inv = 1.f / (float)max(cnt, 1);
    float4 b = __ldg((const float4*)bias + f4);
    float4 r = __ldg((const float4*)(rt + (size_t)row * CH) + f4);

    float4 v;
    v.x = fmaf(acc.x, inv, b.x) + r.x;
    v.y = fmaf(acc.y, inv, b.y) + r.y;
    v.z = fmaf(acc.z, inv, b.z) + r.z;
    v.w = fmaf(acc.w, inv, b.w) + r.w;

    float s = v.x * v.x + v.y * v.y + v.z * v.z + v.w * v.w;
    s += __shfl_xor_sync(0xffffffffu, s, 1);
    s += __shfl_xor_sync(0xffffffffu, s, 2);
    s += __shfl_xor_sync(0xffffffffu, s, 4);
    float rinv = 1.f / fmaxf(sqrtf(s), CEPS);

    float4 o;
    o.x = v.x * rinv; o.y = v.y * rinv; o.z = v.z * rinv; o.w = v.w * rinv;
    if (LAYER == 0) {
        o.x = fmaxf(o.x, 0.f); o.y = fmaxf(o.y, 0.f);
        o.z = fmaxf(o.z, 0.f); o.w = fmaxf(o.w, 0.f);
    }
    if (g == 0)
        ((float4*)(out + (size_t)row * CH))[f4] = o;
}

// ============================================================
// proj1 (SIMT)
// ============================================================
__global__ __launch_bounds__(256) void proj1_kernel(
    const float* __restrict__ wl1, const float* __restrict__ wr1)
{
    __shared__ float swl[CH * CH];
    __shared__ float swr[CH * CH];
    int tid = threadIdx.x;
    for (int idx = tid; idx < CH * CH; idx += 256) {
        int j = idx >> 5, k = idx & 31;
        swl[k * CH + j] = wl1[idx];
        swr[k * CH + j] = wr1[idx];
    }
    __syncthreads();

    int lane = tid & 31;
    int warp = blockIdx.x * 8 + (tid >> 5);
    int rb = warp * 4;

    const float4* h4 = (const float4*)g_h;
    size_t b0 = (size_t)rb * 8;

    float al[4] = {0.f, 0.f, 0.f, 0.f};
    float ar[4] = {0.f, 0.f, 0.f, 0.f};

    #pragma unroll
    for (int k4 = 0; k4 < 8; k4++) {
        float4 v[4];
        #pragma unroll
        for (int i = 0; i < 4; i++) v[i] = h4[b0 + (size_t)i * 8 + k4];
        int kb = k4 * 4;
        float wlr[4], wrr[4];
        #pragma unroll
        for (int d = 0; d < 4; d++) {
            wlr[d] = swl[(kb + d) * CH + lane];
            wrr[d] = swr[(kb + d) * CH + lane];
        }
        #pragma unroll
        for (int i = 0; i < 4; i++) {
            al[i] = fmaf(v[i].x, wlr[0], al[i]);
            al[i] = fmaf(v[i].y, wlr[1], al[i]);
            al[i] = fmaf(v[i].z, wlr[2], al[i]);
            al[i] = fmaf(v[i].w, wlr[3], al[i]);
            ar[i] = fmaf(v[i].x, wrr[0], ar[i]);
            ar[i] = fmaf(v[i].y, wrr[1], ar[i]);
            ar[i] = fmaf(v[i].z, wrr[2], ar[i]);
            ar[i] = fmaf(v[i].w, wrr[3], ar[i]);
        }
    }

    #pragma unroll
    for (int i = 0; i < 4; i++) {
        int r = rb + i;
        g_z1[(size_t)r * CH + lane] = al[i];
        if (r < CN2) g_r1[(size_t)r * CH + lane] = ar[i];
    }
}

// ============================================================
extern "C" void kernel_launch(void* const* d_in, const int* in_sizes, int n_in,
                              void* d_out, int out_size)
{
    const float* x    = (const float*)d_in[0];
    const int*   src0 = (const int*)d_in[1];
    const int*   tgt0 = (const int*)d_in[2];
    const int*   src1 = (const int*)d_in[3];
    const int*   tgt1 = (const int*)d_in[4];
    const float* wl0  = (const float*)d_in[5];
    const float* bl0  = (const float*)d_in[6];
    const float* wr0  = (const float*)d_in[7];
    const float* wl1  = (const float*)d_in[8];
    const float* bl1  = (const float*)d_in[9];
    const float* wr1  = (const float*)d_in[10];
    float* out = (float*)d_out;

    initprep_kernel<<<416, 256>>>(wl0, wr0);                      // 0
    hist_both_kernel<<<3072, 256>>>(tgt0, tgt1);                  // 1
    scanA_both_kernel<<<192, 256>>>();                            // 2
    gemm0_kernel<<<CN0 / 128, 256>>>(x);                          // 3 <- ncu
    scanB_both_kernel<<<1, 256>>>();                              // 4
    bucket_both_kernel<<<3072, 256>>>(src0, tgt0, src1, tgt1);    // 5
    aggfin_kernel<0><<<CN1 / 8, 256>>>(bl0, nullptr);             // 6
    proj1_kernel<<<CN1 / 32, 256>>>(wl1, wr1);                    // 7
    aggfin_kernel<1><<<CN2 / 8, 256>>>(bl1, out);                 // 8
}

// round 10
// speedup vs baseline: 1.1767x; 1.1767x over previous
#include <cuda_runtime.h>
#include <cuda_bf16.h>

#define CN0 262144
#define CN1 131072
#define CN2 65536
#define CE0 2097152
#define CE1 1048576
#define CIN 128
#define CH  32
#define CEPS 1e-12f

typedef unsigned int uint;

// ---- scratch (device globals; referenced from DEVICE code only) ----
__device__ float g_y0[(size_t)CN0 * CH];    // x @ wl0^T      (32 MB)
__device__ float g_r0[(size_t)CN1 * CH];    // x[:N1] @ wr0^T (16 MB)
__device__ float g_h [(size_t)CN1 * CH];    // layer-0 output (16 MB)

__device__ __nv_bfloat16 g_whi[64 * CIN];
__device__ __nv_bfloat16 g_wlo[64 * CIN];

__device__ int g_cnt0[CN1];
__device__ int g_cur0[CN1];
__device__ int g_offl0[CN1];
__device__ int g_part0[CN1 / 1024];
__device__ int g_eid0[CE0];

__device__ int g_cnt1[CN2];
__device__ int g_cur1[CN2];
__device__ int g_offl1[CN2];
__device__ int g_part1[CN2 / 1024];
__device__ int g_eid1[CE1];

__device__ __forceinline__ uint pkbf(float a, float b) {
    __nv_bfloat162 t = __halves2bfloat162(__float2bfloat16(a), __float2bfloat16(b));
    return *reinterpret_cast<uint*>(&t);
}
__device__ __forceinline__ void mma_bf16(float* d, const uint* a, uint b0, uint b1) {
    asm volatile(
        "mma.sync.aligned.m16n8k16.row.col.f32.bf16.bf16.f32 "
        "{%0,%1,%2,%3}, {%4,%5,%6,%7}, {%8,%9}, {%0,%1,%2,%3};"
        : "+f"(d[0]), "+f"(d[1]), "+f"(d[2]), "+f"(d[3])
        : "r"(a[0]), "r"(a[1]), "r"(a[2]), "r"(a[3]), "r"(b0), "r"(b1));
}

// ============================================================
// zero: cnt0/cur0/cnt1/cur1 -> 0  (98304 int4 slots)
// ============================================================
__global__ __launch_bounds__(256) void zero_kernel()
{
    int t = blockIdx.x * 256 + threadIdx.x;
    const int4 z = make_int4(0, 0, 0, 0);
    if (t < 32768)       ((int4*)g_cnt0)[t] = z;
    else if (t < 65536)  ((int4*)g_cur0)[t - 32768] = z;
    else if (t < 81920)  ((int4*)g_cnt1)[t - 65536] = z;
    else                 ((int4*)g_cur1)[t - 81920] = z;
}

// ============================================================
// prepw: split [wl0;wr0] into bf16 hi + residual lo.
// ============================================================
__global__ __launch_bounds__(256) void prepw_kernel(
    const float* __restrict__ wl0, const float* __restrict__ wr0)
{
    int i = blockIdx.x * 256 + threadIdx.x;   // 8192
    float v = (i < 32 * CIN) ? wl0[i] : wr0[i - 32 * CIN];
    __nv_bfloat16 h = __float2bfloat16(v);
    g_whi[i] = h;
    g_wlo[i] = __float2bfloat16(v - __bfloat162float(h));
}

// ============================================================
// gemm0: mma.sync bf16-split GEMM (unchanged from R7)
// ============================================================
#define BSTRIDE 68

__global__ __launch_bounds__(256) void gemm0_kernel(const float* __restrict__ x)
{
    __shared__ uint sbh[64 * BSTRIDE];
    __shared__ uint sbl[64 * BSTRIDE];

    int tid = threadIdx.x;
    int wid = tid >> 5, lane = tid & 31;

    {
        const uint* whi = (const uint*)g_whi;
        const uint* wlo = (const uint*)g_wlo;
        #pragma unroll
        for (int c = tid; c < 4096; c += 256) {
            int r = c >> 6, k = c & 63;
            sbh[r * BSTRIDE + k] = __ldg(whi + c);
            sbl[r * BSTRIDE + k] = __ldg(wlo + c);
        }
    }
    __syncthreads();

    int mrow = lane >> 2;
    int c = lane & 3;
    int nl = lane >> 2;

    int row0 = blockIdx.x * 128 + wid * 16 + mrow;
    const float2* x2 = (const float2*)x;
    size_t base0 = (size_t)row0 * 64 + c;
    size_t base1 = base0 + 8 * 64;

    float d[8][4];
    #pragma unroll
    for (int n = 0; n < 8; n++)
        #pragma unroll
        for (int j = 0; j < 4; j++) d[n][j] = 0.f;

    #pragma unroll
    for (int ks = 0; ks < 8; ks++) {
        float2 p0 = __ldg(&x2[base0 + ks * 8]);
        float2 p1 = __ldg(&x2[base1 + ks * 8]);
        float2 p2 = __ldg(&x2[base0 + ks * 8 + 4]);
        float2 p3 = __ldg(&x2[base1 + ks * 8 + 4]);

        uint ah[4], al[4];
        ah[0] = pkbf(p0.x, p0.y);
        ah[1] = pkbf(p1.x, p1.y);
        ah[2] = pkbf(p2.x, p2.y);
        ah[3] = pkbf(p3.x, p3.y);
        {
            __nv_bfloat162 h0 = *(__nv_bfloat162*)&ah[0];
            __nv_bfloat162 h1 = *(__nv_bfloat162*)&ah[1];
            __nv_bfloat162 h2 = *(__nv_bfloat162*)&ah[2];
            __nv_bfloat162 h3 = *(__nv_bfloat162*)&ah[3];
            al[0] = pkbf(p0.x - __bfloat162float(h0.x), p0.y - __bfloat162float(h0.y));
            al[1] = pkbf(p1.x - __bfloat162float(h1.x), p1.y - __bfloat162float(h1.y));
            al[2] = pkbf(p2.x - __bfloat162float(h2.x), p2.y - __bfloat162float(h2.y));
            al[3] = pkbf(p3.x - __bfloat162float(h3.x), p3.y - __bfloat162float(h3.y));
        }

        #pragma unroll
        for (int n = 0; n < 8; n++) {
            int bidx = (n * 8 + nl) * BSTRIDE + ks * 8 + c;
            uint bh0 = sbh[bidx], bh1 = sbh[bidx + 4];
            uint bl0 = sbl[bidx], bl1 = sbl[bidx + 4];
            mma_bf16(d[n], ah, bh0, bh1);
            mma_bf16(d[n], al, bh0, bh1);
            mma_bf16(d[n], ah, bl0, bl1);
        }
    }

    int rA = row0;
    int rB = row0 + 8;
    #pragma unroll
    for (int n = 0; n < 8; n++) {
        int col = (n & 3) * 8 + c * 2;
        if (n < 4) {
            *(float2*)(g_y0 + (size_t)rA * CH + col) = make_float2(d[n][0], d[n][1]);
            *(float2*)(g_y0 + (size_t)rB * CH + col) = make_float2(d[n][2], d[n][3]);
        } else if (rA < CN1) {
            *(float2*)(g_r0 + (size_t)rA * CH + col) = make_float2(d[n][0], d[n][1]);
            *(float2*)(g_r0 + (size_t)rB * CH + col) = make_float2(d[n][2], d[n][3]);
        }
    }
}

// ============================================================
// hist_both: blocks [0,2048) layer0, [2048,3072) layer1.
// ============================================================
__global__ __launch_bounds__(256) void hist_both_kernel(
    const int* __restrict__ tgt0, const int* __restrict__ tgt1)
{
    int blk = blockIdx.x;
    const int* tgt;
    int* cnt;
    int eb;
    if (blk < 2048) { tgt = tgt0; cnt = g_cnt0; eb = blk; }
    else            { tgt = tgt1; cnt = g_cnt1; eb = blk - 2048; }
    int b = (eb * 256 + threadIdx.x) * 4;
    int4 t = __ldg((const int4*)(tgt + b));
    atomicAdd(&cnt[t.x], 1);
    atomicAdd(&cnt[t.y], 1);
    atomicAdd(&cnt[t.z], 1);
    atomicAdd(&cnt[t.w], 1);
}

// ============================================================
// scanA_both: blocks [0,128) layer0 tiles, [128,192) layer1.
// ============================================================
__global__ __launch_bounds__(256) void scanA_both_kernel()
{
    int blk = blockIdx.x;
    const int* cnt;
    int* offl;
    int* part;
    int tile;
    if (blk < 128) { cnt = g_cnt0; offl = g_offl0; part = g_part0; tile = blk; }
    else           { cnt = g_cnt1; offl = g_offl1; part = g_part1; tile = blk - 128; }

    __shared__ int wsum[8];
    int tid = threadIdx.x;
    int base = tile * 1024 + tid * 4;
    int4 c = __ldg((const int4*)(cnt + base));
    int s1 = c.x + c.y, s2 = s1 + c.z, s3 = s2 + c.w;

    int lane = tid & 31, w = tid >> 5;
    int v = s3;
    #pragma unroll
    for (int o = 1; o < 32; o <<= 1) {
        int t = __shfl_up_sync(0xffffffffu, v, o);
        if (lane >= o) v += t;
    }
    int thr_excl = v - s3;
    if (lane == 31) wsum[w] = v;
    __syncthreads();
    if (w == 0) {
        int ws = (lane < 8) ? wsum[lane] : 0;
        #pragma unroll
        for (int o = 1; o < 8; o <<= 1) {
            int t = __shfl_up_sync(0xffffffffu, ws, o);
            if (lane >= o) ws += t;
        }
        if (lane < 8) wsum[lane] = ws;
    }
    __syncthreads();
    int wexcl = (w == 0) ? 0 : wsum[w - 1];
    int e = wexcl + thr_excl;

    int4 o4;
    o4.x = e; o4.y = e + c.x; o4.z = e + s1; o4.w = e + s2;
    *(int4*)(offl + base) = o4;
    if (tid == 255) part[tile] = wsum[7];
}

// ============================================================
// scanB_both: one block; two exclusive scans (128 + 64).
// ============================================================
__global__ __launch_bounds__(256) void scanB_both_kernel()
{
    __shared__ int ws[8];
    int tid = threadIdx.x;
    bool L1 = tid >= 128;
    int n = L1 ? 64 : 128;
    int idx = L1 ? tid - 128 : tid;
    int* part = L1 ? g_part1 : g_part0;

    int valid = idx < n && tid < 192;
    int v = valid ? part[idx] : 0;
    int lane = tid & 31, w = tid >> 5;
    int x = v;
    #pragma unroll
    for (int o = 1; o < 32; o <<= 1) {
        int t = __shfl_up_sync(0xffffffffu, x, o);
        if (lane >= o) x += t;
    }
    if (lane == 31 && w < 6) ws[w] = x;
    __syncthreads();
    if (tid == 0) {
        int a = 0;
        #pragma unroll
        for (int i = 0; i < 4; i++) { int t = ws[i]; ws[i] = a; a += t; }
    }
    if (tid == 128) {
        int a = 0;
        #pragma unroll
        for (int i = 4; i < 6; i++) { int t = ws[i]; ws[i] = a; a += t; }
    }
    __syncthreads();
    if (valid) part[idx] = (x - v) + ws[w];
}

// ============================================================
// bucket_both: pos = offl(t)+part(tile)+cur(t)++; eid[pos]=src.
// ============================================================
__global__ __launch_bounds__(256) void bucket_both_kernel(
    const int* __restrict__ src0, const int* __restrict__ tgt0,
    const int* __restrict__ src1, const int* __restrict__ tgt1)
{
    int blk = blockIdx.x;
    const int* src; const int* tgt;
    const int* offl; const int* part;
    int* cur; int* eid;
    int eb;
    if (blk < 2048) {
        src = src0; tgt = tgt0; offl = g_offl0; part = g_part0;
        cur = g_cur0; eid = g_eid0; eb = blk;
    } else {
        src = src1; tgt = tgt1; offl = g_offl1; part = g_part1;
        cur = g_cur1; eid = g_eid1; eb = blk - 2048;
    }

    int b = (eb * 256 + threadIdx.x) * 4;
    int4 t = __ldg((const int4*)(tgt + b));
    int4 s = __ldg((const int4*)(src + b));
    #pragma unroll
    for (int i = 0; i < 4; i++) {
        int ti = (i == 0) ? t.x : (i == 1) ? t.y : (i == 2) ? t.z : t.w;
        int si = (i == 0) ? s.x : (i == 1) ? s.y : (i == 2) ? s.z : s.w;
        int off = __ldg(offl + ti) + __ldg(part + (ti >> 10));
        int pos = off + atomicAdd(&cur[ti], 1);
        eid[pos] = si;
    }
}

// ============================================================
// aggfin0: warp per row; batched gather of y0 + fused
// mean + bl0 + r0 + L2norm + relu -> g_h
// ============================================================
__global__ __launch_bounds__(256) void aggfin0_kernel(const float* __restrict__ bias)
{
    int lane = threadIdx.x & 31;
    int row = blockIdx.x * 8 + (threadIdx.x >> 5);
    int g = lane >> 3;
    int f4 = lane & 7;

    int cnt = __ldg(g_cnt0 + row);
    int start = __ldg(g_offl0 + row) + __ldg(g_part0 + (row >> 10));

    float4 acc = make_float4(0.f, 0.f, 0.f, 0.f);
    int i = g;
    for (; i + 12 < cnt; i += 16) {
        int s0 = __ldg(g_eid0 + start + i);
        int s1 = __ldg(g_eid0 + start + i + 4);
        int s2 = __ldg(g_eid0 + start + i + 8);
        int s3 = __ldg(g_eid0 + start + i + 12);
        float4 v0 = __ldg((const float4*)(g_y0 + (size_t)s0 * CH) + f4);
        float4 v1 = __ldg((const float4*)(g_y0 + (size_t)s1 * CH) + f4);
        float4 v2 = __ldg((const float4*)(g_y0 + (size_t)s2 * CH) + f4);
        float4 v3 = __ldg((const float4*)(g_y0 + (size_t)s3 * CH) + f4);
        acc.x += (v0.x + v1.x) + (v2.x + v3.x);
        acc.y += (v0.y + v1.y) + (v2.y + v3.y);
        acc.z += (v0.z + v1.z) + (v2.z + v3.z);
        acc.w += (v0.w + v1.w) + (v2.w + v3.w);
    }
    for (; i < cnt; i += 4) {
        int s = __ldg(g_eid0 + start + i);
        float4 v = __ldg((const float4*)(g_y0 + (size_t)s * CH) + f4);
        acc.x += v.x; acc.y += v.y; acc.z += v.z; acc.w += v.w;
    }
    #pragma unroll
    for (int o = 8; o <= 16; o <<= 1) {
        acc.x += __shfl_xor_sync(0xffffffffu, acc.x, o);
        acc.y += __shfl_xor_sync(0xffffffffu, acc.y, o);
        acc.z += __shfl_xor_sync(0xffffffffu, acc.z, o);
        acc.w += __shfl_xor_sync(0xffffffffu, acc.w, o);
    }

    float inv = 1.f / (float)max(cnt, 1);
    float4 b = __ldg((const float4*)bias + f4);
    float4 r = __ldg((const float4*)(g_r0 + (size_t)row * CH) + f4);

    float4 v;
    v.x = fmaf(acc.x, inv, b.x) + r.x;
    v.y = fmaf(acc.y, inv, b.y) + r.y;
    v.z = fmaf(acc.z, inv, b.z) + r.z;
    v.w = fmaf(acc.w, inv, b.w) + r.w;

    float s = v.x * v.x + v.y * v.y + v.z * v.z + v.w * v.w;
    s += __shfl_xor_sync(0xffffffffu, s, 1);
    s += __shfl_xor_sync(0xffffffffu, s, 2);
    s += __shfl_xor_sync(0xffffffffu, s, 4);
    float rinv = 1.f / fmaxf(sqrtf(s), CEPS);

    float4 o;
    o.x = fmaxf(v.x * rinv, 0.f);
    o.y = fmaxf(v.y * rinv, 0.f);
    o.z = fmaxf(v.z * rinv, 0.f);
    o.w = fmaxf(v.w * rinv, 0.f);
    if (g == 0)
        ((float4*)(g_h + (size_t)row * CH))[f4] = o;
}

// ============================================================
// aggfin1: warp per target row. Gather-mean of h rows, then
// out_j = bl1[j] + mean . wl1[j,:] + root . wr1[j,:], L2norm.
// (mean commutes with the linear map -> matches reference exactly)
// ============================================================
__global__ __launch_bounds__(256) void aggfin1_kernel(
    const float* __restrict__ bl1,
    const float* __restrict__ wl1, const float* __restrict__ wr1,
    float* __restrict__ out)
{
    __shared__ float swl[CH * 33];     // padded stride: bank (j+d)%32 distinct
    __shared__ float swr[CH * 33];
    __shared__ float smean[8][CH];
    __shared__ float sroot[8][CH];

    int tid = threadIdx.x;
    for (int i = tid; i < CH * CH; i += 256) {
        int j = i >> 5, d = i & 31;
        swl[j * 33 + d] = __ldg(wl1 + i);
        swr[j * 33 + d] = __ldg(wr1 + i);
    }
    __syncthreads();

    int lane = tid & 31, w = tid >> 5;
    int row = blockIdx.x * 8 + w;
    int g = lane >> 3;
    int f4 = lane & 7;

    int cnt = __ldg(g_cnt1 + row);
    int start = __ldg(g_offl1 + row) + __ldg(g_part1 + (row >> 10));

    float4 acc = make_float4(0.f, 0.f, 0.f, 0.f);
    int i = g;
    for (; i + 12 < cnt; i += 16) {
        int s0 = __ldg(g_eid1 + start + i);
        int s1 = __ldg(g_eid1 + start + i + 4);
        int s2 = __ldg(g_eid1 + start + i + 8);
        int s3 = __ldg(g_eid1 + start + i + 12);
        float4 v0 = __ldg((const float4*)(g_h + (size_t)s0 * CH) + f4);
        float4 v1 = __ldg((const float4*)(g_h + (size_t)s1 * CH) + f4);
        float4 v2 = __ldg((const float4*)(g_h + (size_t)s2 * CH) + f4);
        float4 v3 = __ldg((const float4*)(g_h + (size_t)s3 * CH) + f4);
        acc.x += (v0.x + v1.x) + (v2.x + v3.x);
        acc.y += (v0.y + v1.y) + (v2.y + v3.y);
        acc.z += (v0.z + v1.z) + (v2.z + v3.z);
        acc.w += (v0.w + v1.w) + (v2.w + v3.w);
    }
    for (; i < cnt; i += 4) {
        int s = __ldg(g_eid1 + start + i);
        float4 v = __ldg((const float4*)(g_h + (size_t)s * CH) + f4);
        acc.x += v.x; acc.y += v.y; acc.z += v.z; acc.w += v.w;
    }
    #pragma unroll
    for (int o = 8; o <= 16; o <<= 1) {
        acc.x += __shfl_xor_sync(0xffffffffu, acc.x, o);
        acc.y += __shfl_xor_sync(0xffffffffu, acc.y, o);
        acc.z += __shfl_xor_sync(0xffffffffu, acc.z, o);
        acc.w += __shfl_xor_sync(0xffffffffu, acc.w, o);
    }

    float inv = 1.f / (float)max(cnt, 1);
    if (g == 0) {
        float4 r = __ldg((const float4*)(g_h + (size_t)row * CH) + f4);
        smean[w][f4 * 4 + 0] = acc.x * inv;
        smean[w][f4 * 4 + 1] = acc.y * inv;
        smean[w][f4 * 4 + 2] = acc.z * inv;
        smean[w][f4 * 4 + 3] = acc.w * inv;
        sroot[w][f4 * 4 + 0] = r.x;
        sroot[w][f4 * 4 + 1] = r.y;
        sroot[w][f4 * 4 + 2] = r.z;
        sroot[w][f4 * 4 + 3] = r.w;
    }
    __syncwarp();

    // lane j computes output dim j
    float v = __ldg(bl1 + lane);
    #pragma unroll
    for (int d = 0; d < CH; d++) {
        v = fmaf(smean[w][d], swl[lane * 33 + d], v);
        v = fmaf(sroot[w][d], swr[lane * 33 + d], v);
    }

    float s = v * v;
    #pragma unroll
    for (int o = 1; o < 32; o <<= 1)
        s += __shfl_xor_sync(0xffffffffu, s, o);
    float rinv = 1.f / fmaxf(sqrtf(s), CEPS);

    out[(size_t)row * CH + lane] = v * rinv;
}

// ============================================================
extern "C" void kernel_launch(void* const* d_in, const int* in_sizes, int n_in,
                              void* d_out, int out_size)
{
    const float* x    = (const float*)d_in[0];
    const int*   src0 = (const int*)d_in[1];
    const int*   tgt0 = (const int*)d_in[2];
    const int*   src1 = (const int*)d_in[3];
    const int*   tgt1 = (const int*)d_in[4];
    const float* wl0  = (const float*)d_in[5];
    const float* bl0  = (const float*)d_in[6];
    const float* wr0  = (const float*)d_in[7];
    const float* wl1  = (const float*)d_in[8];
    const float* bl1  = (const float*)d_in[9];
    const float* wr1  = (const float*)d_in[10];
    float* out = (float*)d_out;

    zero_kernel<<<384, 256>>>();                                  // 0
    prepw_kernel<<<32, 256>>>(wl0, wr0);                          // 1
    gemm0_kernel<<<CN0 / 128, 256>>>(x);                          // 2
    hist_both_kernel<<<3072, 256>>>(tgt0, tgt1);                  // 3 <- ncu
    scanA_both_kernel<<<192, 256>>>();                            // 4
    scanB_both_kernel<<<1, 256>>>();                              // 5
    bucket_both_kernel<<<3072, 256>>>(src0, tgt0, src1, tgt1);    // 6
    aggfin0_kernel<<<CN1 / 8, 256>>>(bl0);                        // 7
    aggfin1_kernel<<<CN2 / 8, 256>>>(bl1, wl1, wr1, out);         // 8
}